// round 5
// baseline (speedup 1.0000x reference)
#include <cuda_runtime.h>
#include <cuda_bf16.h>
#include <math.h>
#include <stdint.h>

#define B_ 2
#define N_ 2048
#define K_ 32
#define H_ 128
#define DFF_ 512
#define L_ 3
#define NNODE (B_*N_)
#define NE (B_*N_*K_)
#define EPSF 1e-6f

// weight area offsets (elements), layout [n][k]
#define OFF_WE 0
#define OFF_WQ 8192
#define OFF_L0 24576
#define LSTRIDE 212992
#define OW1A 0        // packed with W1C -> N=256 block
#define OW1C 16384
#define OW1E 32768
#define OW2  49152
#define OW3  65536
#define OWI  81920
#define OWO  147456
#define WTOT (24576 + 3*212992)

// epilogue modes
#define EPI_F32     0
#define EPI_SPLIT   1
#define EPI_LN      2
#define EPI_COMBINE 3
#define EPI_AGG     4

// ---------------- device scratch ----------------
__device__ float g_Ebuf[(size_t)NE*64];
__device__ __nv_bfloat16 g_t0h[(size_t)NE*H_], g_t0l[(size_t)NE*H_];
__device__ __nv_bfloat16 g_t1h[(size_t)NE*H_], g_t1l[(size_t)NE*H_];
__device__ __nv_bfloat16 g_hEh[(size_t)NE*H_], g_hEl[(size_t)NE*H_];
__device__ __nv_bfloat16 g_ffh[NNODE*DFF_], g_ffl[NNODE*DFF_];
__device__ float g_hV[NNODE*H_];
__device__ float g_nAC[(size_t)NNODE*256];
__device__ float g_dh[NNODE*H_];
__device__ float g_AD[NNODE*3];
__device__ float g_Of[NNODE*9];
__device__ int   g_Eidx[NE];
__device__ float g_Dnb[NE];
__device__ __nv_bfloat16 g_wh[WTOT];
__device__ __nv_bfloat16 g_wl[WTOT];
__device__ float g_b1pad[3*256];

__device__ __forceinline__ float sgnf(float x) { return (x > 0.f) ? 1.f : ((x < 0.f) ? -1.f : 0.f); }
__device__ __forceinline__ float clampc(float x) { return fminf(fmaxf(x, -1.f + EPSF), 1.f - EPSF); }

__device__ __forceinline__ float block_sum128(float v, float* red) {
    int o = threadIdx.x;
    red[o] = v; __syncthreads();
    #pragma unroll
    for (int s = 64; s > 0; s >>= 1) { if (o < s) red[o] += red[o + s]; __syncthreads(); }
    float r = red[0]; __syncthreads();
    return r;
}

// ---------------- kNN ----------------
__global__ void knn_kernel(const float* __restrict__ X, const float* __restrict__ mask) {
    __shared__ float sD[N_];
    __shared__ float red[256];
    __shared__ int   redi[256];
    int nf = blockIdx.x;
    int b = nf / N_;
    int tid = threadIdx.x;
    float xi0 = X[nf*3+0], xi1 = X[nf*3+1], xi2 = X[nf*3+2];
    float mi = mask[nf];
    for (int j = tid; j < N_; j += 256) {
        float dx = xi0 - X[(b*N_+j)*3+0];
        float dy = xi1 - X[(b*N_+j)*3+1];
        float dz = xi2 - X[(b*N_+j)*3+2];
        float m2 = mi * mask[b*N_+j];
        sD[j] = m2 * sqrtf(dx*dx + dy*dy + dz*dz + EPSF);
    }
    __syncthreads();
    float mx = -3.4e38f;
    for (int j = tid; j < N_; j += 256) mx = fmaxf(mx, sD[j]);
    red[tid] = mx; __syncthreads();
    #pragma unroll
    for (int s = 128; s > 0; s >>= 1) { if (tid < s) red[tid] = fmaxf(red[tid], red[tid+s]); __syncthreads(); }
    float rowmax = red[0]; __syncthreads();
    for (int j = tid; j < N_; j += 256) {
        float m2 = mi * mask[b*N_+j];
        sD[j] = sD[j] + (1.f - m2) * rowmax;
    }
    __syncthreads();
    for (int k = 0; k < K_; k++) {
        float best = 3.4e38f; int bi = 0x7fffffff;
        for (int j = tid; j < N_; j += 256) {
            float v = sD[j];
            if (v < best || (v == best && j < bi)) { best = v; bi = j; }
        }
        red[tid] = best; redi[tid] = bi; __syncthreads();
        #pragma unroll
        for (int s = 128; s > 0; s >>= 1) {
            if (tid < s) {
                float v = red[tid+s]; int vi = redi[tid+s];
                if (v < red[tid] || (v == red[tid] && vi < redi[tid])) { red[tid] = v; redi[tid] = vi; }
            }
            __syncthreads();
        }
        if (tid == 0) {
            int e = nf*K_ + k;
            g_Eidx[e] = redi[0];
            g_Dnb[e]  = red[0];
            sD[redi[0]] = 3.4e38f;
        }
        __syncthreads();
    }
}

// ---------------- frames ----------------
__global__ void frames_kernel(const float* __restrict__ X) {
    int nf = blockIdx.x*blockDim.x + threadIdx.x;
    if (nf >= NNODE) return;
    int n = nf % N_;
    float* ad = &g_AD[nf*3];
    float* of = &g_Of[nf*9];
    if (n < 1 || n > N_-3) {
        ad[0]=ad[1]=ad[2]=0.f;
        #pragma unroll
        for (int t=0;t<9;t++) of[t]=0.f;
        return;
    }
    float p[4][3];
    #pragma unroll
    for (int t=0;t<4;t++) { p[t][0]=X[(nf-1+t)*3+0]; p[t][1]=X[(nf-1+t)*3+1]; p[t][2]=X[(nf-1+t)*3+2]; }
    float u2[3], u1[3], u0[3];
    #pragma unroll
    for (int c=0;c<3;c++) { u2[c]=p[1][c]-p[0][c]; u1[c]=p[2][c]-p[1][c]; u0[c]=p[3][c]-p[2][c]; }
    auto normv = [](float* v) {
        float l = sqrtf(v[0]*v[0]+v[1]*v[1]+v[2]*v[2]);
        float il = 1.f / fmaxf(l, 1e-12f);
        v[0]*=il; v[1]*=il; v[2]*=il;
    };
    normv(u2); normv(u1); normv(u0);
    float n2[3] = { u2[1]*u1[2]-u2[2]*u1[1], u2[2]*u1[0]-u2[0]*u1[2], u2[0]*u1[1]-u2[1]*u1[0] };
    float n1[3] = { u1[1]*u0[2]-u1[2]*u0[1], u1[2]*u0[0]-u1[0]*u0[2], u1[0]*u0[1]-u1[1]*u0[0] };
    normv(n2); normv(n1);
    float cosA = clampc(-(u1[0]*u0[0]+u1[1]*u0[1]+u1[2]*u0[2]));
    float sinA = sqrtf(fmaxf(1.f - cosA*cosA, 0.f));
    float cosD = clampc(n2[0]*n1[0]+n2[1]*n1[1]+n2[2]*n1[2]);
    float sinD = sqrtf(fmaxf(1.f - cosD*cosD, 0.f));
    float sg = sgnf(u2[0]*n1[0]+u2[1]*n1[1]+u2[2]*n1[2]);
    ad[0] = cosA; ad[1] = sinA*cosD; ad[2] = sinA*sg*sinD;
    float o1[3] = { u2[0]-u1[0], u2[1]-u1[1], u2[2]-u1[2] };
    normv(o1);
    float cr[3] = { o1[1]*n2[2]-o1[2]*n2[1], o1[2]*n2[0]-o1[0]*n2[2], o1[0]*n2[1]-o1[1]*n2[0] };
    of[0]=o1[0]; of[1]=o1[1]; of[2]=o1[2];
    of[3]=n2[0]; of[4]=n2[1]; of[5]=n2[2];
    of[6]=cr[0]; of[7]=cr[1]; of[8]=cr[2];
}

// ---------------- node init ----------------
__global__ void node_init_kernel(const float* __restrict__ Wn, const float* __restrict__ bn,
                                 const float* __restrict__ gn, const float* __restrict__ hn,
                                 const float* __restrict__ Wv, const float* __restrict__ bv) {
    __shared__ float sV[H_];
    __shared__ float red[H_];
    int n = blockIdx.x, o = threadIdx.x;
    float a0 = g_AD[n*3+0], a1 = g_AD[n*3+1], a2 = g_AD[n*3+2];
    float t = a0*Wn[o] + a1*Wn[H_+o] + a2*Wn[2*H_+o] + bn[o];
    float mu = block_sum128(t, red) * (1.f/H_);
    float dv = t - mu;
    float var = block_sum128(dv*dv, red) * (1.f/(H_-1));
    float y = gn[o]*dv/(sqrtf(var+EPSF)+EPSF) + hn[o];
    sV[o] = y; __syncthreads();
    float acc = bv[o];
    #pragma unroll 8
    for (int i = 0; i < H_; i++) acc += sV[i]*Wv[i*H_+o];
    g_hV[n*H_+o] = acc;
}

// ---------------- edge features (stride 64, zero-padded) ----------------
__global__ void edge_feat_kernel(const float* __restrict__ X) {
    int e = blockIdx.x*blockDim.x + threadIdx.x;
    if (e >= NE) return;
    int nf = e / K_;
    int n = nf % N_, b = nf / N_;
    int j = g_Eidx[e];
    float* E = &g_Ebuf[(size_t)e*64];
    float d = (float)(j - n);
    const float lc = -logf(10000.f) / 16.f;
    #pragma unroll
    for (int f = 0; f < 8; f++) {
        float freq = expf((2.f*f)*lc);
        float ang = d*freq;
        E[f]   = cosf(ang);
        E[8+f] = sinf(ang);
    }
    float D = g_Dnb[e];
    #pragma unroll
    for (int m = 0; m < 16; m++) {
        float mu = (20.f/15.f)*m;
        float t = (D - mu)*0.8f;
        E[16+m] = expf(-t*t);
    }
    float Om[9], Ob[9];
    #pragma unroll
    for (int t=0;t<9;t++) Om[t] = g_Of[nf*9+t];
    #pragma unroll
    for (int t=0;t<9;t++) Ob[t] = g_Of[(b*N_+j)*9+t];
    float dx0 = X[(b*N_+j)*3+0]-X[nf*3+0];
    float dx1 = X[(b*N_+j)*3+1]-X[nf*3+1];
    float dx2 = X[(b*N_+j)*3+2]-X[nf*3+2];
    float du[3];
    #pragma unroll
    for (int i=0;i<3;i++) du[i] = Om[i*3+0]*dx0 + Om[i*3+1]*dx1 + Om[i*3+2]*dx2;
    float l = sqrtf(du[0]*du[0]+du[1]*du[1]+du[2]*du[2]);
    float il = 1.f / fmaxf(l, 1e-12f);
    du[0]*=il; du[1]*=il; du[2]*=il;
    float R[3][3];
    #pragma unroll
    for (int i=0;i<3;i++)
        #pragma unroll
        for (int c=0;c<3;c++)
            R[i][c] = Om[0*3+i]*Ob[0*3+c] + Om[1*3+i]*Ob[1*3+c] + Om[2*3+i]*Ob[2*3+c];
    float Rxx=R[0][0], Ryy=R[1][1], Rzz=R[2][2];
    float m0 = 0.5f*sqrtf(fabsf(1.f + Rxx - Ryy - Rzz));
    float m1 = 0.5f*sqrtf(fabsf(1.f - Rxx + Ryy - Rzz));
    float m2 = 0.5f*sqrtf(fabsf(1.f - Rxx - Ryy + Rzz));
    float s0 = sgnf(R[2][1]-R[1][2]);
    float s1 = sgnf(R[0][2]-R[2][0]);
    float s2 = sgnf(R[1][0]-R[0][1]);
    float w  = sqrtf(fmaxf(1.f + Rxx + Ryy + Rzz, 0.f)) * 0.5f;
    float q[4] = { s0*m0, s1*m1, s2*m2, w };
    float ql = sqrtf(q[0]*q[0]+q[1]*q[1]+q[2]*q[2]+q[3]*q[3]);
    float iql = 1.f / fmaxf(ql, 1e-12f);
    E[32]=du[0]; E[33]=du[1]; E[34]=du[2];
    E[35]=q[0]*iql; E[36]=q[1]*iql; E[37]=q[2]*iql; E[38]=q[3]*iql;
    #pragma unroll
    for (int t = 39; t < 64; t++) E[t] = 0.f;
}

// ---------------- single weight-prep kernel: transpose + hi/lo split + b1 pack ----------------
__global__ void prep_all(const float* __restrict__ We, const float* __restrict__ Wq,
                         const float* __restrict__ lW1, const float* __restrict__ lW2,
                         const float* __restrict__ lW3, const float* __restrict__ lWi,
                         const float* __restrict__ lWo, const float* __restrict__ lb1) {
    int idx = blockIdx.x*256 + threadIdx.x;
    if (idx >= WTOT + 768) return;
    if (idx >= WTOT) {
        int r = idx - WTOT; int l = r >> 8; int c = r & 255;
        g_b1pad[l*256 + c] = (c < 128) ? lb1[l*128 + c] : 0.f;
        return;
    }
    const float* src; int local, Ksrc, Kpad, srcN;
    if (idx < 8192)       { src = We; local = idx;        Ksrc = 39;  Kpad = 64;  srcN = 128; }
    else if (idx < 24576) { src = Wq; local = idx - 8192; Ksrc = 128; Kpad = 128; srcN = 128; }
    else {
        int r = idx - 24576; int l = r / LSTRIDE; int o = r % LSTRIDE;
        Ksrc = 128; Kpad = 128; srcN = 128;
        if (o < 16384)       { src = lW1 + (size_t)l*49152;          local = o; }
        else if (o < 32768)  { src = lW1 + (size_t)l*49152 + 32768;  local = o - 16384; }  // W1C (rows 256..383)
        else if (o < 49152)  { src = lW1 + (size_t)l*49152 + 16384;  local = o - 32768; }  // W1E (rows 128..255)
        else if (o < 65536)  { src = lW2 + (size_t)l*16384; local = o - 49152; }
        else if (o < 81920)  { src = lW3 + (size_t)l*16384; local = o - 65536; }
        else if (o < 147456) { src = lWi + (size_t)l*65536; local = o - 81920;  srcN = 512; }
        else                 { src = lWo + (size_t)l*65536; local = o - 147456; Ksrc = 512; Kpad = 512; srcN = 128; }
    }
    int n = local / Kpad, k = local - n*Kpad;
    float v = (k < Ksrc) ? src[(size_t)k*srcN + n] : 0.f;
    __nv_bfloat16 bh = __float2bfloat16(v);
    g_wh[idx] = bh;
    g_wl[idx] = __float2bfloat16(v - __bfloat162float(bh));
}

// ---------------- split-bf16 mma.sync GEMM with fused epilogues ----------------
#define STR 40
#define STRW 20
#define STG 132
#define SMEM_DYN (128*STG*4 + 4*STG*4)   // 69696

__device__ __forceinline__ void mma16816(float* d, const uint32_t* a, uint32_t b0, uint32_t b1) {
    asm volatile(
        "mma.sync.aligned.m16n8k16.row.col.f32.bf16.bf16.f32 "
        "{%0,%1,%2,%3}, {%4,%5,%6,%7}, {%8,%9}, {%0,%1,%2,%3};"
        : "+f"(d[0]), "+f"(d[1]), "+f"(d[2]), "+f"(d[3])
        : "r"(a[0]), "r"(a[1]), "r"(a[2]), "r"(a[3]), "r"(b0), "r"(b1));
}
__device__ __forceinline__ uint32_t pack_hi2(float d0, float d1) {
    return (uint32_t)__bfloat16_as_ushort(__float2bfloat16(d0)) |
           ((uint32_t)__bfloat16_as_ushort(__float2bfloat16(d1)) << 16);
}
__device__ __forceinline__ uint32_t pack_lo2(float d0, float d1) {
    float r0 = d0 - __bfloat162float(__float2bfloat16(d0));
    float r1 = d1 - __bfloat162float(__float2bfloat16(d1));
    return (uint32_t)__bfloat16_as_ushort(__float2bfloat16(r0)) |
           ((uint32_t)__bfloat16_as_ushort(__float2bfloat16(r1)) << 16);
}

__global__ __launch_bounds__(256, 2) void mma_gemm(
    const float* __restrict__ Af,
    const __nv_bfloat16* __restrict__ Ahi, const __nv_bfloat16* __restrict__ Alo,
    const __nv_bfloat16* __restrict__ Bhi, const __nv_bfloat16* __restrict__ Blo,
    const float* __restrict__ bias,
    float* __restrict__ Cf, __nv_bfloat16* __restrict__ Chi, __nv_bfloat16* __restrict__ Clo,
    int K, int ldc, int mode, int relu,
    const float* __restrict__ gln, const float* __restrict__ hln,
    const float* __restrict__ mask, float* __restrict__ hv)
{
    extern __shared__ __align__(16) char smem[];
    __nv_bfloat16* sAh = (__nv_bfloat16*)smem;
    __nv_bfloat16* sAl = sAh + 128*STR;
    __nv_bfloat16* sBh = sAl + 128*STR;
    __nv_bfloat16* sBl = sBh + 128*STR;
    float* stage = (float*)smem;
    float* xbuf  = (float*)(smem + 128*STG*4);

    int tid = threadIdx.x, lane = tid & 31, w = tid >> 5;
    int wm = w & 3, wn = w >> 2;
    int row0 = blockIdx.y*128, colb = blockIdx.x*128;
    int g = lane >> 2, t = lane & 3;

    float acc[2][8][4];
    #pragma unroll
    for (int mt=0;mt<2;mt++)
        #pragma unroll
        for (int nt=0;nt<8;nt++)
            #pragma unroll
            for (int q=0;q<4;q++) acc[mt][nt][q] = 0.f;

    const int nk = K >> 5;
    for (int kc = 0; kc < nk; kc++) {
        if (Af) {
            #pragma unroll
            for (int i = 0; i < 4; i++) {
                int idx = tid + i*256;
                int r = idx >> 3, kq = (idx & 7) * 4;
                float4 va = *reinterpret_cast<const float4*>(Af + (size_t)(row0+r)*K + kc*32 + kq);
                float vv[4] = {va.x, va.y, va.z, va.w};
                unsigned short hh[4], ll[4];
                #pragma unroll
                for (int q = 0; q < 4; q++) {
                    __nv_bfloat16 bh = __float2bfloat16(vv[q]);
                    hh[q] = __bfloat16_as_ushort(bh);
                    ll[q] = __bfloat16_as_ushort(__float2bfloat16(vv[q] - __bfloat162float(bh)));
                }
                *reinterpret_cast<uint2*>(&sAh[r*STR + kq]) =
                    make_uint2((uint32_t)hh[0] | ((uint32_t)hh[1]<<16), (uint32_t)hh[2] | ((uint32_t)hh[3]<<16));
                *reinterpret_cast<uint2*>(&sAl[r*STR + kq]) =
                    make_uint2((uint32_t)ll[0] | ((uint32_t)ll[1]<<16), (uint32_t)ll[2] | ((uint32_t)ll[3]<<16));
            }
        } else {
            #pragma unroll
            for (int i = 0; i < 4; i++) {
                int idx = tid + i*256;
                int r = idx >> 3, kq = (idx & 7) * 4;
                *reinterpret_cast<uint2*>(&sAh[r*STR + kq]) =
                    *reinterpret_cast<const uint2*>(Ahi + (size_t)(row0+r)*K + kc*32 + kq);
                *reinterpret_cast<uint2*>(&sAl[r*STR + kq]) =
                    *reinterpret_cast<const uint2*>(Alo + (size_t)(row0+r)*K + kc*32 + kq);
            }
        }
        #pragma unroll
        for (int i = 0; i < 4; i++) {
            int idx = tid + i*256;
            int n = idx >> 3, kq = (idx & 7) * 4;
            *reinterpret_cast<uint2*>(&sBh[n*STR + kq]) =
                *reinterpret_cast<const uint2*>(Bhi + (size_t)(colb+n)*K + kc*32 + kq);
            *reinterpret_cast<uint2*>(&sBl[n*STR + kq]) =
                *reinterpret_cast<const uint2*>(Blo + (size_t)(colb+n)*K + kc*32 + kq);
        }
        __syncthreads();

        const uint32_t* pAh = reinterpret_cast<const uint32_t*>(sAh);
        const uint32_t* pAl = reinterpret_cast<const uint32_t*>(sAl);
        const uint32_t* pBh = reinterpret_cast<const uint32_t*>(sBh);
        const uint32_t* pBl = reinterpret_cast<const uint32_t*>(sBl);

        #pragma unroll
        for (int ks = 0; ks < 2; ks++) {
            uint32_t ah[2][4], al[2][4];
            #pragma unroll
            for (int mt = 0; mt < 2; mt++) {
                int rb = wm*32 + mt*16;
                int base = (rb+g)*STRW + ks*8 + t;
                int base8 = (rb+g+8)*STRW + ks*8 + t;
                ah[mt][0] = pAh[base];   ah[mt][1] = pAh[base8];
                ah[mt][2] = pAh[base+4]; ah[mt][3] = pAh[base8+4];
                al[mt][0] = pAl[base];   al[mt][1] = pAl[base8];
                al[mt][2] = pAl[base+4]; al[mt][3] = pAl[base8+4];
            }
            #pragma unroll
            for (int nt = 0; nt < 8; nt++) {
                int nb = wn*64 + nt*8;
                int bbase = (nb+g)*STRW + ks*8 + t;
                uint32_t bh0 = pBh[bbase], bh1 = pBh[bbase+4];
                uint32_t bl0 = pBl[bbase], bl1 = pBl[bbase+4];
                #pragma unroll
                for (int mt = 0; mt < 2; mt++) {
                    mma16816(acc[mt][nt], ah[mt], bh0, bh1);
                    mma16816(acc[mt][nt], ah[mt], bl0, bl1);
                    mma16816(acc[mt][nt], al[mt], bh0, bh1);
                }
            }
        }
        __syncthreads();
    }

    // ------------- epilogues -------------
    if (mode == EPI_F32 || mode == EPI_SPLIT || mode == EPI_COMBINE) {
        #pragma unroll
        for (int mt = 0; mt < 2; mt++) {
            #pragma unroll
            for (int hh = 0; hh < 2; hh++) {
                int grow = row0 + wm*32 + mt*16 + g + hh*8;
                const float* na = nullptr; const float* ncp = nullptr;
                if (mode == EPI_COMBINE) {
                    int e = grow;
                    int nf = e >> 5;
                    int bb = nf >> 11;
                    int j = g_Eidx[e];
                    na  = &g_nAC[(size_t)nf*256];
                    ncp = &g_nAC[((size_t)(bb*N_ + j))*256 + 128];
                }
                #pragma unroll
                for (int nt = 0; nt < 8; nt++) {
                    int cl = wn*64 + nt*8 + t*2;
                    float d0 = acc[mt][nt][hh*2+0];
                    float d1 = acc[mt][nt][hh*2+1];
                    if (bias) { d0 += __ldg(&bias[colb+cl]); d1 += __ldg(&bias[colb+cl+1]); }
                    if (mode == EPI_COMBINE) {
                        d0 = fmaxf(d0 + na[cl]  + ncp[cl],  0.f);
                        d1 = fmaxf(d1 + na[cl+1] + ncp[cl+1], 0.f);
                    } else if (relu) {
                        d0 = fmaxf(d0, 0.f); d1 = fmaxf(d1, 0.f);
                    }
                    if (mode == EPI_F32) {
                        *reinterpret_cast<float2*>(Cf + (size_t)grow*ldc + colb + cl) = make_float2(d0, d1);
                    } else {
                        *reinterpret_cast<uint32_t*>(Chi + (size_t)grow*ldc + colb + cl) = pack_hi2(d0, d1);
                        *reinterpret_cast<uint32_t*>(Clo + (size_t)grow*ldc + colb + cl) = pack_lo2(d0, d1);
                    }
                }
            }
        }
    } else if (mode == EPI_LN) {
        // stage, then per-row LayerNorm, then split-store
        #pragma unroll
        for (int mt = 0; mt < 2; mt++)
            #pragma unroll
            for (int hh = 0; hh < 2; hh++) {
                int row = wm*32 + mt*16 + g + hh*8;
                #pragma unroll
                for (int nt = 0; nt < 8; nt++) {
                    int cl = wn*64 + nt*8 + t*2;
                    float d0 = acc[mt][nt][hh*2+0] + __ldg(&bias[cl]);
                    float d1 = acc[mt][nt][hh*2+1] + __ldg(&bias[cl+1]);
                    stage[row*STG + cl] = d0;
                    stage[row*STG + cl+1] = d1;
                }
            }
        __syncthreads();
        int row = tid >> 1, half = tid & 1;
        const float* rp = &stage[row*STG + half*64];
        float s = 0.f;
        #pragma unroll 16
        for (int q = 0; q < 64; q++) s += rp[q];
        s += __shfl_xor_sync(0xffffffffu, s, 1);
        float mu = s * (1.f/128.f);
        float ss = 0.f;
        #pragma unroll 16
        for (int q = 0; q < 64; q++) { float d = rp[q]-mu; ss += d*d; }
        ss += __shfl_xor_sync(0xffffffffu, ss, 1);
        float inv = 1.f / (sqrtf(ss*(1.f/127.f) + EPSF) + EPSF);
        int grow = row0 + row;
        uint32_t* ph = reinterpret_cast<uint32_t*>(Chi + (size_t)grow*ldc + half*64);
        uint32_t* pl = reinterpret_cast<uint32_t*>(Clo + (size_t)grow*ldc + half*64);
        #pragma unroll 8
        for (int q = 0; q < 64; q += 2) {
            int c = half*64 + q;
            float y0 = gln[c]*(rp[q]-mu)*inv + hln[c];
            float y1 = gln[c+1]*(rp[q+1]-mu)*inv + hln[c+1];
            ph[q>>1] = pack_hi2(y0, y1);
            pl[q>>1] = pack_lo2(y0, y1);
        }
    } else { // EPI_AGG: masked message sum + residual + LayerNorm -> hv
        #pragma unroll
        for (int mt = 0; mt < 2; mt++)
            #pragma unroll
            for (int hh = 0; hh < 2; hh++) {
                int row = wm*32 + mt*16 + g + hh*8;
                int e = row0 + row;
                int nf = e >> 5;
                int bb = nf >> 11;
                int j = g_Eidx[e];
                float matt = __ldg(&mask[nf]) * __ldg(&mask[bb*N_ + j]);
                #pragma unroll
                for (int nt = 0; nt < 8; nt++) {
                    int cl = wn*64 + nt*8 + t*2;
                    float d0 = (acc[mt][nt][hh*2+0] + __ldg(&bias[cl])) * matt;
                    float d1 = (acc[mt][nt][hh*2+1] + __ldg(&bias[cl+1])) * matt;
                    stage[row*STG + cl] = d0;
                    stage[row*STG + cl+1] = d1;
                }
            }
        __syncthreads();
        for (int it = tid; it < 512; it += 256) {
            int nd = it >> 7, c = it & 127;
            float s = 0.f;
            #pragma unroll 8
            for (int r = 0; r < 32; r++) s += stage[(nd*32+r)*STG + c];
            int gnode = (row0 >> 5) + nd;
            xbuf[nd*STG + c] = g_hV[gnode*H_ + c] + s * (1.f/30.f);
        }
        __syncthreads();
        if (w < 4) {
            int nd = w;
            int gnode = (row0 >> 5) + nd;
            float x[4];
            #pragma unroll
            for (int q = 0; q < 4; q++) x[q] = xbuf[nd*STG + lane*4 + q];
            float s = x[0]+x[1]+x[2]+x[3];
            #pragma unroll
            for (int off = 16; off > 0; off >>= 1) s += __shfl_xor_sync(0xffffffffu, s, off);
            float mu = s * (1.f/128.f);
            float ss = 0.f;
            #pragma unroll
            for (int q = 0; q < 4; q++) { float d = x[q]-mu; ss += d*d; }
            #pragma unroll
            for (int off = 16; off > 0; off >>= 1) ss += __shfl_xor_sync(0xffffffffu, ss, off);
            float inv = 1.f / (sqrtf(ss*(1.f/127.f) + EPSF) + EPSF);
            float4 o;
            o.x = gln[lane*4+0]*(x[0]-mu)*inv + hln[lane*4+0];
            o.y = gln[lane*4+1]*(x[1]-mu)*inv + hln[lane*4+1];
            o.z = gln[lane*4+2]*(x[2]-mu)*inv + hln[lane*4+2];
            o.w = gln[lane*4+3]*(x[3]-mu)*inv + hln[lane*4+3];
            *reinterpret_cast<float4*>(&hv[gnode*H_ + lane*4]) = o;
        }
    }
}

// ---------------- residual FFN LN + mask ----------------
__global__ void resln_kernel(float* __restrict__ dst, const float* __restrict__ mask,
                             const float* __restrict__ g1, const float* __restrict__ h1) {
    __shared__ float red[H_];
    int n = blockIdx.x, o = threadIdx.x;
    float x = g_hV[n*H_+o] + g_dh[n*H_+o];
    float mu = block_sum128(x, red) * (1.f/H_);
    float dv = x - mu;
    float var = block_sum128(dv*dv, red) * (1.f/(H_-1));
    float y = g1[o]*dv/(sqrtf(var+EPSF)+EPSF) + h1[o];
    dst[n*H_+o] = mask[n]*y;
}

// ---------------- host ----------------
extern "C" void kernel_launch(void* const* d_in, const int* in_sizes, int n_in,
                              void* d_out, int out_size) {
    const float* X    = (const float*)d_in[0];
    const float* mask = (const float*)d_in[1];
    const float* Wn   = (const float*)d_in[2];
    const float* bn   = (const float*)d_in[3];
    const float* gn   = (const float*)d_in[4];
    const float* hn   = (const float*)d_in[5];
    const float* We   = (const float*)d_in[6];
    const float* be   = (const float*)d_in[7];
    const float* ge   = (const float*)d_in[8];
    const float* he   = (const float*)d_in[9];
    const float* Wv   = (const float*)d_in[10];
    const float* bv   = (const float*)d_in[11];
    const float* Wq   = (const float*)d_in[12];
    const float* bq   = (const float*)d_in[13];
    const float* lW1  = (const float*)d_in[14];
    const float* lb1  = (const float*)d_in[15];
    const float* lW2  = (const float*)d_in[16];
    const float* lb2  = (const float*)d_in[17];
    const float* lW3  = (const float*)d_in[18];
    const float* lb3  = (const float*)d_in[19];
    const float* lWi  = (const float*)d_in[20];
    const float* lbi  = (const float*)d_in[21];
    const float* lWo  = (const float*)d_in[22];
    const float* lbo  = (const float*)d_in[23];
    const float* lg0  = (const float*)d_in[24];
    const float* lh0  = (const float*)d_in[25];
    const float* lg1  = (const float*)d_in[26];
    const float* lh1  = (const float*)d_in[27];

    static int s_init = 0;
    if (!s_init) {
        cudaFuncSetAttribute(mma_gemm, cudaFuncAttributeMaxDynamicSharedMemorySize, SMEM_DYN);
        s_init = 1;
    }

    float *Ebuf, *hV, *nAC, *dh, *b1pad;
    __nv_bfloat16 *wh, *wl, *t0h, *t0l, *t1h, *t1l, *hEh, *hEl, *ffh, *ffl;
    cudaGetSymbolAddress((void**)&Ebuf, g_Ebuf);
    cudaGetSymbolAddress((void**)&hV,   g_hV);
    cudaGetSymbolAddress((void**)&nAC,  g_nAC);
    cudaGetSymbolAddress((void**)&dh,   g_dh);
    cudaGetSymbolAddress((void**)&b1pad,g_b1pad);
    cudaGetSymbolAddress((void**)&wh,   g_wh);
    cudaGetSymbolAddress((void**)&wl,   g_wl);
    cudaGetSymbolAddress((void**)&t0h,  g_t0h);
    cudaGetSymbolAddress((void**)&t0l,  g_t0l);
    cudaGetSymbolAddress((void**)&t1h,  g_t1h);
    cudaGetSymbolAddress((void**)&t1l,  g_t1l);
    cudaGetSymbolAddress((void**)&hEh,  g_hEh);
    cudaGetSymbolAddress((void**)&hEl,  g_hEl);
    cudaGetSymbolAddress((void**)&ffh,  g_ffh);
    cudaGetSymbolAddress((void**)&ffl,  g_ffl);

    auto gemm = [&](const float* Af, const __nv_bfloat16* Ah, const __nv_bfloat16* Al,
                    size_t woff, const float* bias, float* Cf, __nv_bfloat16* Ch, __nv_bfloat16* Cl,
                    int M, int N, int Kd, int ldcv, int mode, int relu,
                    const float* gl, const float* hl, const float* mk, float* hvp) {
        dim3 grid(N/128, M/128);
        mma_gemm<<<grid, 256, SMEM_DYN>>>(Af, Ah, Al, wh+woff, wl+woff, bias,
                                          Cf, Ch, Cl, Kd, ldcv, mode, relu, gl, hl, mk, hvp);
    };

    // weights (single launch)
    prep_all<<<(WTOT+768+255)/256, 256>>>(We, Wq, lW1, lW2, lW3, lWi, lWo, lb1);

    // Phase A
    knn_kernel<<<NNODE, 256>>>(X, mask);
    frames_kernel<<<(NNODE+255)/256, 256>>>(X);
    node_init_kernel<<<NNODE, 128>>>(Wn, bn, gn, hn, Wv, bv);
    edge_feat_kernel<<<(NE+255)/256, 256>>>(X);
    // E = LN(Ebuf @ We + be)  -> t0 (split)
    gemm(Ebuf, nullptr, nullptr, OFF_WE, be, nullptr, t0h, t0l,
         NE, 128, 64, 128, EPI_LN, 0, ge, he, nullptr, nullptr);
    // hE = t0 @ Wq + bq  -> hE (split)
    gemm(nullptr, t0h, t0l, OFF_WQ, bq, nullptr, hEh, hEl,
         NE, 128, 128, 128, EPI_SPLIT, 0, nullptr, nullptr, nullptr, nullptr);

    // Phase B
    for (int l = 0; l < L_; l++) {
        size_t base = OFF_L0 + (size_t)l*LSTRIDE;
        // nAC = hV @ [W1A | W1C] (+b1 on first half)
        gemm(hV, nullptr, nullptr, base + OW1A, b1pad + l*256, nAC, nullptr, nullptr,
             NNODE, 256, 128, 256, EPI_F32, 0, nullptr, nullptr, nullptr, nullptr);
        // t0 = relu(hE @ W1E + nA[center] + nC[neighbor])  (split)
        gemm(nullptr, hEh, hEl, base + OW1E, nullptr, nullptr, t0h, t0l,
             NE, 128, 128, 128, EPI_COMBINE, 0, nullptr, nullptr, nullptr, nullptr);
        // t1 = relu(t0 @ W2 + b2)  (split)
        gemm(nullptr, t0h, t0l, base + OW2, lb2 + l*H_, nullptr, t1h, t1l,
             NE, 128, 128, 128, EPI_SPLIT, 1, nullptr, nullptr, nullptr, nullptr);
        // hV = LN(hV + sum_k((t1 @ W3 + b3) * m_att) / 30)   (fused aggregate)
        gemm(nullptr, t1h, t1l, base + OW3, lb3 + l*H_, nullptr, nullptr, nullptr,
             NE, 128, 128, 128, EPI_AGG, 0, lg0 + l*H_, lh0 + l*H_, mask, hV);
        // ff = relu(hV @ Wi + bi)  (split)
        gemm(hV, nullptr, nullptr, base + OWI, lbi + l*DFF_, nullptr, ffh, ffl,
             NNODE, 512, 128, 512, EPI_SPLIT, 1, nullptr, nullptr, nullptr, nullptr);
        // dh = ff @ Wo + bo
        gemm(nullptr, ffh, ffl, base + OWO, lbo + l*H_, dh, nullptr, nullptr,
             NNODE, 128, 512, 128, EPI_F32, 0, nullptr, nullptr, nullptr, nullptr);
        float* dst = (l == L_-1) ? (float*)d_out : hV;
        resln_kernel<<<NNODE, H_>>>(dst, mask, lg1 + l*H_, lh1 + l*H_);
    }
}

// round 6
// speedup vs baseline: 1.0027x; 1.0027x over previous
#include <cuda_runtime.h>
#include <cuda_bf16.h>
#include <math.h>
#include <stdint.h>

#define B_ 2
#define N_ 2048
#define K_ 32
#define H_ 128
#define DFF_ 512
#define L_ 3
#define NNODE (B_*N_)
#define NE (B_*N_*K_)
#define EPSF 1e-6f

// weight area offsets (elements), layout [n][k]
#define OFF_WE 0
#define OFF_WQ 8192
#define OFF_L0 24576
#define LSTRIDE 212992
#define OW1A 0        // packed with W1C -> N=256 block
#define OW1C 16384
#define OW1E 32768
#define OW2  49152
#define OW3  65536
#define OWI  81920
#define OWO  147456
#define WTOT (24576 + 3*212992)

// epilogue modes
#define EPI_F32     0
#define EPI_SPLIT   1
#define EPI_LN      2
#define EPI_COMBINE 3
#define EPI_AGG     4

// ---------------- device scratch ----------------
__device__ float g_Ebuf[(size_t)NE*64];
__device__ __nv_bfloat16 g_t0h[(size_t)NE*H_], g_t0l[(size_t)NE*H_];
__device__ __nv_bfloat16 g_t1h[(size_t)NE*H_], g_t1l[(size_t)NE*H_];
__device__ __nv_bfloat16 g_hEh[(size_t)NE*H_], g_hEl[(size_t)NE*H_];
__device__ __nv_bfloat16 g_ffh[NNODE*DFF_], g_ffl[NNODE*DFF_];
__device__ float g_hV[NNODE*H_];
__device__ float g_nAC[(size_t)NNODE*256];
__device__ float g_dh[NNODE*H_];
__device__ float g_AD[NNODE*3];
__device__ float g_Of[NNODE*9];
__device__ int   g_Eidx[NE];
__device__ float g_Dnb[NE];
__device__ __nv_bfloat16 g_wh[WTOT];
__device__ __nv_bfloat16 g_wl[WTOT];
__device__ float g_b1pad[3*256];

__device__ __forceinline__ float sgnf(float x) { return (x > 0.f) ? 1.f : ((x < 0.f) ? -1.f : 0.f); }
__device__ __forceinline__ float clampc(float x) { return fminf(fmaxf(x, -1.f + EPSF), 1.f - EPSF); }

__device__ __forceinline__ float block_sum128(float v, float* red) {
    int o = threadIdx.x;
    red[o] = v; __syncthreads();
    #pragma unroll
    for (int s = 64; s > 0; s >>= 1) { if (o < s) red[o] += red[o + s]; __syncthreads(); }
    float r = red[0]; __syncthreads();
    return r;
}

// ---------------- kNN ----------------
__global__ void knn_kernel(const float* __restrict__ X, const float* __restrict__ mask) {
    __shared__ float sD[N_];
    __shared__ float red[256];
    __shared__ int   redi[256];
    int nf = blockIdx.x;
    int b = nf / N_;
    int tid = threadIdx.x;
    float xi0 = X[nf*3+0], xi1 = X[nf*3+1], xi2 = X[nf*3+2];
    float mi = mask[nf];
    for (int j = tid; j < N_; j += 256) {
        float dx = xi0 - X[(b*N_+j)*3+0];
        float dy = xi1 - X[(b*N_+j)*3+1];
        float dz = xi2 - X[(b*N_+j)*3+2];
        float m2 = mi * mask[b*N_+j];
        sD[j] = m2 * sqrtf(dx*dx + dy*dy + dz*dz + EPSF);
    }
    __syncthreads();
    float mx = -3.4e38f;
    for (int j = tid; j < N_; j += 256) mx = fmaxf(mx, sD[j]);
    red[tid] = mx; __syncthreads();
    #pragma unroll
    for (int s = 128; s > 0; s >>= 1) { if (tid < s) red[tid] = fmaxf(red[tid], red[tid+s]); __syncthreads(); }
    float rowmax = red[0]; __syncthreads();
    for (int j = tid; j < N_; j += 256) {
        float m2 = mi * mask[b*N_+j];
        sD[j] = sD[j] + (1.f - m2) * rowmax;
    }
    __syncthreads();
    for (int k = 0; k < K_; k++) {
        float best = 3.4e38f; int bi = 0x7fffffff;
        for (int j = tid; j < N_; j += 256) {
            float v = sD[j];
            if (v < best || (v == best && j < bi)) { best = v; bi = j; }
        }
        red[tid] = best; redi[tid] = bi; __syncthreads();
        #pragma unroll
        for (int s = 128; s > 0; s >>= 1) {
            if (tid < s) {
                float v = red[tid+s]; int vi = redi[tid+s];
                if (v < red[tid] || (v == red[tid] && vi < redi[tid])) { red[tid] = v; redi[tid] = vi; }
            }
            __syncthreads();
        }
        if (tid == 0) {
            int e = nf*K_ + k;
            g_Eidx[e] = redi[0];
            g_Dnb[e]  = red[0];
            sD[redi[0]] = 3.4e38f;
        }
        __syncthreads();
    }
}

// ---------------- frames ----------------
__global__ void frames_kernel(const float* __restrict__ X) {
    int nf = blockIdx.x*blockDim.x + threadIdx.x;
    if (nf >= NNODE) return;
    int n = nf % N_;
    float* ad = &g_AD[nf*3];
    float* of = &g_Of[nf*9];
    if (n < 1 || n > N_-3) {
        ad[0]=ad[1]=ad[2]=0.f;
        #pragma unroll
        for (int t=0;t<9;t++) of[t]=0.f;
        return;
    }
    float p[4][3];
    #pragma unroll
    for (int t=0;t<4;t++) { p[t][0]=X[(nf-1+t)*3+0]; p[t][1]=X[(nf-1+t)*3+1]; p[t][2]=X[(nf-1+t)*3+2]; }
    float u2[3], u1[3], u0[3];
    #pragma unroll
    for (int c=0;c<3;c++) { u2[c]=p[1][c]-p[0][c]; u1[c]=p[2][c]-p[1][c]; u0[c]=p[3][c]-p[2][c]; }
    auto normv = [](float* v) {
        float l = sqrtf(v[0]*v[0]+v[1]*v[1]+v[2]*v[2]);
        float il = 1.f / fmaxf(l, 1e-12f);
        v[0]*=il; v[1]*=il; v[2]*=il;
    };
    normv(u2); normv(u1); normv(u0);
    float n2[3] = { u2[1]*u1[2]-u2[2]*u1[1], u2[2]*u1[0]-u2[0]*u1[2], u2[0]*u1[1]-u2[1]*u1[0] };
    float n1[3] = { u1[1]*u0[2]-u1[2]*u0[1], u1[2]*u0[0]-u1[0]*u0[2], u1[0]*u0[1]-u1[1]*u0[0] };
    normv(n2); normv(n1);
    float cosA = clampc(-(u1[0]*u0[0]+u1[1]*u0[1]+u1[2]*u0[2]));
    float sinA = sqrtf(fmaxf(1.f - cosA*cosA, 0.f));
    float cosD = clampc(n2[0]*n1[0]+n2[1]*n1[1]+n2[2]*n1[2]);
    float sinD = sqrtf(fmaxf(1.f - cosD*cosD, 0.f));
    float sg = sgnf(u2[0]*n1[0]+u2[1]*n1[1]+u2[2]*n1[2]);
    ad[0] = cosA; ad[1] = sinA*cosD; ad[2] = sinA*sg*sinD;
    float o1[3] = { u2[0]-u1[0], u2[1]-u1[1], u2[2]-u1[2] };
    normv(o1);
    float cr[3] = { o1[1]*n2[2]-o1[2]*n2[1], o1[2]*n2[0]-o1[0]*n2[2], o1[0]*n2[1]-o1[1]*n2[0] };
    of[0]=o1[0]; of[1]=o1[1]; of[2]=o1[2];
    of[3]=n2[0]; of[4]=n2[1]; of[5]=n2[2];
    of[6]=cr[0]; of[7]=cr[1]; of[8]=cr[2];
}

// ---------------- node init ----------------
__global__ void node_init_kernel(const float* __restrict__ Wn, const float* __restrict__ bn,
                                 const float* __restrict__ gn, const float* __restrict__ hn,
                                 const float* __restrict__ Wv, const float* __restrict__ bv) {
    __shared__ float sV[H_];
    __shared__ float red[H_];
    int n = blockIdx.x, o = threadIdx.x;
    float a0 = g_AD[n*3+0], a1 = g_AD[n*3+1], a2 = g_AD[n*3+2];
    float t = a0*Wn[o] + a1*Wn[H_+o] + a2*Wn[2*H_+o] + bn[o];
    float mu = block_sum128(t, red) * (1.f/H_);
    float dv = t - mu;
    float var = block_sum128(dv*dv, red) * (1.f/(H_-1));
    float y = gn[o]*dv/(sqrtf(var+EPSF)+EPSF) + hn[o];
    sV[o] = y; __syncthreads();
    float acc = bv[o];
    #pragma unroll 8
    for (int i = 0; i < H_; i++) acc += sV[i]*Wv[i*H_+o];
    g_hV[n*H_+o] = acc;
}

// ---------------- edge features (stride 64, zero-padded) ----------------
__global__ void edge_feat_kernel(const float* __restrict__ X) {
    int e = blockIdx.x*blockDim.x + threadIdx.x;
    if (e >= NE) return;
    int nf = e / K_;
    int n = nf % N_, b = nf / N_;
    int j = g_Eidx[e];
    float* E = &g_Ebuf[(size_t)e*64];
    float d = (float)(j - n);
    const float lc = -logf(10000.f) / 16.f;
    #pragma unroll
    for (int f = 0; f < 8; f++) {
        float freq = expf((2.f*f)*lc);
        float ang = d*freq;
        E[f]   = cosf(ang);
        E[8+f] = sinf(ang);
    }
    float D = g_Dnb[e];
    #pragma unroll
    for (int m = 0; m < 16; m++) {
        float mu = (20.f/15.f)*m;
        float t = (D - mu)*0.8f;
        E[16+m] = expf(-t*t);
    }
    float Om[9], Ob[9];
    #pragma unroll
    for (int t=0;t<9;t++) Om[t] = g_Of[nf*9+t];
    #pragma unroll
    for (int t=0;t<9;t++) Ob[t] = g_Of[(b*N_+j)*9+t];
    float dx0 = X[(b*N_+j)*3+0]-X[nf*3+0];
    float dx1 = X[(b*N_+j)*3+1]-X[nf*3+1];
    float dx2 = X[(b*N_+j)*3+2]-X[nf*3+2];
    float du[3];
    #pragma unroll
    for (int i=0;i<3;i++) du[i] = Om[i*3+0]*dx0 + Om[i*3+1]*dx1 + Om[i*3+2]*dx2;
    float l = sqrtf(du[0]*du[0]+du[1]*du[1]+du[2]*du[2]);
    float il = 1.f / fmaxf(l, 1e-12f);
    du[0]*=il; du[1]*=il; du[2]*=il;
    float R[3][3];
    #pragma unroll
    for (int i=0;i<3;i++)
        #pragma unroll
        for (int c=0;c<3;c++)
            R[i][c] = Om[0*3+i]*Ob[0*3+c] + Om[1*3+i]*Ob[1*3+c] + Om[2*3+i]*Ob[2*3+c];
    float Rxx=R[0][0], Ryy=R[1][1], Rzz=R[2][2];
    float m0 = 0.5f*sqrtf(fabsf(1.f + Rxx - Ryy - Rzz));
    float m1 = 0.5f*sqrtf(fabsf(1.f - Rxx + Ryy - Rzz));
    float m2 = 0.5f*sqrtf(fabsf(1.f - Rxx - Ryy + Rzz));
    float s0 = sgnf(R[2][1]-R[1][2]);
    float s1 = sgnf(R[0][2]-R[2][0]);
    float s2 = sgnf(R[1][0]-R[0][1]);
    float w  = sqrtf(fmaxf(1.f + Rxx + Ryy + Rzz, 0.f)) * 0.5f;
    float q[4] = { s0*m0, s1*m1, s2*m2, w };
    float ql = sqrtf(q[0]*q[0]+q[1]*q[1]+q[2]*q[2]+q[3]*q[3]);
    float iql = 1.f / fmaxf(ql, 1e-12f);
    E[32]=du[0]; E[33]=du[1]; E[34]=du[2];
    E[35]=q[0]*iql; E[36]=q[1]*iql; E[37]=q[2]*iql; E[38]=q[3]*iql;
    #pragma unroll
    for (int t = 39; t < 64; t++) E[t] = 0.f;
}

// ---------------- single weight-prep kernel: transpose + hi/lo split + b1 pack ----------------
__global__ void prep_all(const float* __restrict__ We, const float* __restrict__ Wq,
                         const float* __restrict__ lW1, const float* __restrict__ lW2,
                         const float* __restrict__ lW3, const float* __restrict__ lWi,
                         const float* __restrict__ lWo, const float* __restrict__ lb1) {
    int idx = blockIdx.x*256 + threadIdx.x;
    if (idx >= WTOT + 768) return;
    if (idx >= WTOT) {
        int r = idx - WTOT; int l = r >> 8; int c = r & 255;
        g_b1pad[l*256 + c] = (c < 128) ? lb1[l*128 + c] : 0.f;
        return;
    }
    const float* src; int local, Ksrc, Kpad, srcN;
    if (idx < 8192)       { src = We; local = idx;        Ksrc = 39;  Kpad = 64;  srcN = 128; }
    else if (idx < 24576) { src = Wq; local = idx - 8192; Ksrc = 128; Kpad = 128; srcN = 128; }
    else {
        int r = idx - 24576; int l = r / LSTRIDE; int o = r % LSTRIDE;
        Ksrc = 128; Kpad = 128; srcN = 128;
        if (o < 16384)       { src = lW1 + (size_t)l*49152;          local = o; }
        else if (o < 32768)  { src = lW1 + (size_t)l*49152 + 32768;  local = o - 16384; }  // W1C (rows 256..383)
        else if (o < 49152)  { src = lW1 + (size_t)l*49152 + 16384;  local = o - 32768; }  // W1E (rows 128..255)
        else if (o < 65536)  { src = lW2 + (size_t)l*16384; local = o - 49152; }
        else if (o < 81920)  { src = lW3 + (size_t)l*16384; local = o - 65536; }
        else if (o < 147456) { src = lWi + (size_t)l*65536; local = o - 81920;  srcN = 512; }
        else                 { src = lWo + (size_t)l*65536; local = o - 147456; Ksrc = 512; Kpad = 512; srcN = 128; }
    }
    int n = local / Kpad, k = local - n*Kpad;
    float v = (k < Ksrc) ? src[(size_t)k*srcN + n] : 0.f;
    __nv_bfloat16 bh = __float2bfloat16(v);
    g_wh[idx] = bh;
    g_wl[idx] = __float2bfloat16(v - __bfloat162float(bh));
}

// ---------------- split-bf16 mma.sync GEMM with fused epilogues ----------------
#define STR 40
#define STRW 20
#define STG 132
#define SMEM_DYN (128*STG*4 + 4*STG*4)   // 69696

__device__ __forceinline__ void mma16816(float* d, const uint32_t* a, uint32_t b0, uint32_t b1) {
    asm volatile(
        "mma.sync.aligned.m16n8k16.row.col.f32.bf16.bf16.f32 "
        "{%0,%1,%2,%3}, {%4,%5,%6,%7}, {%8,%9}, {%0,%1,%2,%3};"
        : "+f"(d[0]), "+f"(d[1]), "+f"(d[2]), "+f"(d[3])
        : "r"(a[0]), "r"(a[1]), "r"(a[2]), "r"(a[3]), "r"(b0), "r"(b1));
}
__device__ __forceinline__ uint32_t pack_hi2(float d0, float d1) {
    return (uint32_t)__bfloat16_as_ushort(__float2bfloat16(d0)) |
           ((uint32_t)__bfloat16_as_ushort(__float2bfloat16(d1)) << 16);
}
__device__ __forceinline__ uint32_t pack_lo2(float d0, float d1) {
    float r0 = d0 - __bfloat162float(__float2bfloat16(d0));
    float r1 = d1 - __bfloat162float(__float2bfloat16(d1));
    return (uint32_t)__bfloat16_as_ushort(__float2bfloat16(r0)) |
           ((uint32_t)__bfloat16_as_ushort(__float2bfloat16(r1)) << 16);
}

__global__ __launch_bounds__(256, 2) void mma_gemm(
    const float* __restrict__ Af,
    const __nv_bfloat16* __restrict__ Ahi, const __nv_bfloat16* __restrict__ Alo,
    const __nv_bfloat16* __restrict__ Bhi, const __nv_bfloat16* __restrict__ Blo,
    const float* __restrict__ bias,
    float* __restrict__ Cf, __nv_bfloat16* __restrict__ Chi, __nv_bfloat16* __restrict__ Clo,
    int K, int ldc, int mode, int relu,
    const float* __restrict__ gln, const float* __restrict__ hln,
    const float* __restrict__ mask, float* __restrict__ hv)
{
    extern __shared__ __align__(16) char smem[];
    __nv_bfloat16* sAh = (__nv_bfloat16*)smem;
    __nv_bfloat16* sAl = sAh + 128*STR;
    __nv_bfloat16* sBh = sAl + 128*STR;
    __nv_bfloat16* sBl = sBh + 128*STR;
    float* stage = (float*)smem;
    float* xbuf  = (float*)(smem + 128*STG*4);

    int tid = threadIdx.x, lane = tid & 31, w = tid >> 5;
    int wm = w & 3, wn = w >> 2;
    int row0 = blockIdx.y*128, colb = blockIdx.x*128;
    int g = lane >> 2, t = lane & 3;

    float acc[2][8][4];
    #pragma unroll
    for (int mt=0;mt<2;mt++)
        #pragma unroll
        for (int nt=0;nt<8;nt++)
            #pragma unroll
            for (int q=0;q<4;q++) acc[mt][nt][q] = 0.f;

    const int nk = K >> 5;
    for (int kc = 0; kc < nk; kc++) {
        if (Af) {
            #pragma unroll
            for (int i = 0; i < 4; i++) {
                int idx = tid + i*256;
                int r = idx >> 3, kq = (idx & 7) * 4;
                float4 va = *reinterpret_cast<const float4*>(Af + (size_t)(row0+r)*K + kc*32 + kq);
                float vv[4] = {va.x, va.y, va.z, va.w};
                unsigned short hh[4], ll[4];
                #pragma unroll
                for (int q = 0; q < 4; q++) {
                    __nv_bfloat16 bh = __float2bfloat16(vv[q]);
                    hh[q] = __bfloat16_as_ushort(bh);
                    ll[q] = __bfloat16_as_ushort(__float2bfloat16(vv[q] - __bfloat162float(bh)));
                }
                *reinterpret_cast<uint2*>(&sAh[r*STR + kq]) =
                    make_uint2((uint32_t)hh[0] | ((uint32_t)hh[1]<<16), (uint32_t)hh[2] | ((uint32_t)hh[3]<<16));
                *reinterpret_cast<uint2*>(&sAl[r*STR + kq]) =
                    make_uint2((uint32_t)ll[0] | ((uint32_t)ll[1]<<16), (uint32_t)ll[2] | ((uint32_t)ll[3]<<16));
            }
        } else {
            #pragma unroll
            for (int i = 0; i < 4; i++) {
                int idx = tid + i*256;
                int r = idx >> 3, kq = (idx & 7) * 4;
                *reinterpret_cast<uint2*>(&sAh[r*STR + kq]) =
                    *reinterpret_cast<const uint2*>(Ahi + (size_t)(row0+r)*K + kc*32 + kq);
                *reinterpret_cast<uint2*>(&sAl[r*STR + kq]) =
                    *reinterpret_cast<const uint2*>(Alo + (size_t)(row0+r)*K + kc*32 + kq);
            }
        }
        #pragma unroll
        for (int i = 0; i < 4; i++) {
            int idx = tid + i*256;
            int n = idx >> 3, kq = (idx & 7) * 4;
            *reinterpret_cast<uint2*>(&sBh[n*STR + kq]) =
                *reinterpret_cast<const uint2*>(Bhi + (size_t)(colb+n)*K + kc*32 + kq);
            *reinterpret_cast<uint2*>(&sBl[n*STR + kq]) =
                *reinterpret_cast<const uint2*>(Blo + (size_t)(colb+n)*K + kc*32 + kq);
        }
        __syncthreads();

        const uint32_t* pAh = reinterpret_cast<const uint32_t*>(sAh);
        const uint32_t* pAl = reinterpret_cast<const uint32_t*>(sAl);
        const uint32_t* pBh = reinterpret_cast<const uint32_t*>(sBh);
        const uint32_t* pBl = reinterpret_cast<const uint32_t*>(sBl);

        #pragma unroll
        for (int ks = 0; ks < 2; ks++) {
            uint32_t ah[2][4], al[2][4];
            #pragma unroll
            for (int mt = 0; mt < 2; mt++) {
                int rb = wm*32 + mt*16;
                int base = (rb+g)*STRW + ks*8 + t;
                int base8 = (rb+g+8)*STRW + ks*8 + t;
                ah[mt][0] = pAh[base];   ah[mt][1] = pAh[base8];
                ah[mt][2] = pAh[base+4]; ah[mt][3] = pAh[base8+4];
                al[mt][0] = pAl[base];   al[mt][1] = pAl[base8];
                al[mt][2] = pAl[base+4]; al[mt][3] = pAl[base8+4];
            }
            #pragma unroll
            for (int nt = 0; nt < 8; nt++) {
                int nb = wn*64 + nt*8;
                int bbase = (nb+g)*STRW + ks*8 + t;
                uint32_t bh0 = pBh[bbase], bh1 = pBh[bbase+4];
                uint32_t bl0 = pBl[bbase], bl1 = pBl[bbase+4];
                #pragma unroll
                for (int mt = 0; mt < 2; mt++) {
                    mma16816(acc[mt][nt], ah[mt], bh0, bh1);
                    mma16816(acc[mt][nt], ah[mt], bl0, bl1);
                    mma16816(acc[mt][nt], al[mt], bh0, bh1);
                }
            }
        }
        __syncthreads();
    }

    // ------------- epilogues -------------
    if (mode == EPI_F32 || mode == EPI_SPLIT || mode == EPI_COMBINE) {
        #pragma unroll
        for (int mt = 0; mt < 2; mt++) {
            #pragma unroll
            for (int hh = 0; hh < 2; hh++) {
                int grow = row0 + wm*32 + mt*16 + g + hh*8;
                const float* na = nullptr; const float* ncp = nullptr;
                if (mode == EPI_COMBINE) {
                    int e = grow;
                    int nf = e >> 5;
                    int bb = nf >> 11;
                    int j = g_Eidx[e];
                    na  = &g_nAC[(size_t)nf*256];
                    ncp = &g_nAC[((size_t)(bb*N_ + j))*256 + 128];
                }
                #pragma unroll
                for (int nt = 0; nt < 8; nt++) {
                    int cl = wn*64 + nt*8 + t*2;
                    float d0 = acc[mt][nt][hh*2+0];
                    float d1 = acc[mt][nt][hh*2+1];
                    if (bias) { d0 += __ldg(&bias[colb+cl]); d1 += __ldg(&bias[colb+cl+1]); }
                    if (mode == EPI_COMBINE) {
                        d0 = fmaxf(d0 + na[cl]  + ncp[cl],  0.f);
                        d1 = fmaxf(d1 + na[cl+1] + ncp[cl+1], 0.f);
                    } else if (relu) {
                        d0 = fmaxf(d0, 0.f); d1 = fmaxf(d1, 0.f);
                    }
                    if (mode == EPI_F32) {
                        *reinterpret_cast<float2*>(Cf + (size_t)grow*ldc + colb + cl) = make_float2(d0, d1);
                    } else {
                        *reinterpret_cast<uint32_t*>(Chi + (size_t)grow*ldc + colb + cl) = pack_hi2(d0, d1);
                        *reinterpret_cast<uint32_t*>(Clo + (size_t)grow*ldc + colb + cl) = pack_lo2(d0, d1);
                    }
                }
            }
        }
    } else if (mode == EPI_LN) {
        // stage, then per-row LayerNorm, then split-store
        #pragma unroll
        for (int mt = 0; mt < 2; mt++)
            #pragma unroll
            for (int hh = 0; hh < 2; hh++) {
                int row = wm*32 + mt*16 + g + hh*8;
                #pragma unroll
                for (int nt = 0; nt < 8; nt++) {
                    int cl = wn*64 + nt*8 + t*2;
                    float d0 = acc[mt][nt][hh*2+0] + __ldg(&bias[cl]);
                    float d1 = acc[mt][nt][hh*2+1] + __ldg(&bias[cl+1]);
                    stage[row*STG + cl] = d0;
                    stage[row*STG + cl+1] = d1;
                }
            }
        __syncthreads();
        int row = tid >> 1, half = tid & 1;
        const float* rp = &stage[row*STG + half*64];
        float s = 0.f;
        #pragma unroll 16
        for (int q = 0; q < 64; q++) s += rp[q];
        s += __shfl_xor_sync(0xffffffffu, s, 1);
        float mu = s * (1.f/128.f);
        float ss = 0.f;
        #pragma unroll 16
        for (int q = 0; q < 64; q++) { float d = rp[q]-mu; ss += d*d; }
        ss += __shfl_xor_sync(0xffffffffu, ss, 1);
        float inv = 1.f / (sqrtf(ss*(1.f/127.f) + EPSF) + EPSF);
        int grow = row0 + row;
        uint32_t* ph = reinterpret_cast<uint32_t*>(Chi + (size_t)grow*ldc + half*64);
        uint32_t* pl = reinterpret_cast<uint32_t*>(Clo + (size_t)grow*ldc + half*64);
        #pragma unroll 8
        for (int q = 0; q < 64; q += 2) {
            int c = half*64 + q;
            float y0 = gln[c]*(rp[q]-mu)*inv + hln[c];
            float y1 = gln[c+1]*(rp[q+1]-mu)*inv + hln[c+1];
            ph[q>>1] = pack_hi2(y0, y1);
            pl[q>>1] = pack_lo2(y0, y1);
        }
    } else { // EPI_AGG: masked message sum + residual + LayerNorm -> hv
        #pragma unroll
        for (int mt = 0; mt < 2; mt++)
            #pragma unroll
            for (int hh = 0; hh < 2; hh++) {
                int row = wm*32 + mt*16 + g + hh*8;
                int e = row0 + row;
                int nf = e >> 5;
                int bb = nf >> 11;
                int j = g_Eidx[e];
                float matt = __ldg(&mask[nf]) * __ldg(&mask[bb*N_ + j]);
                #pragma unroll
                for (int nt = 0; nt < 8; nt++) {
                    int cl = wn*64 + nt*8 + t*2;
                    float d0 = (acc[mt][nt][hh*2+0] + __ldg(&bias[cl])) * matt;
                    float d1 = (acc[mt][nt][hh*2+1] + __ldg(&bias[cl+1])) * matt;
                    stage[row*STG + cl] = d0;
                    stage[row*STG + cl+1] = d1;
                }
            }
        __syncthreads();
        for (int it = tid; it < 512; it += 256) {
            int nd = it >> 7, c = it & 127;
            float s = 0.f;
            #pragma unroll 8
            for (int r = 0; r < 32; r++) s += stage[(nd*32+r)*STG + c];
            int gnode = (row0 >> 5) + nd;
            xbuf[nd*STG + c] = g_hV[gnode*H_ + c] + s * (1.f/30.f);
        }
        __syncthreads();
        if (w < 4) {
            int nd = w;
            int gnode = (row0 >> 5) + nd;
            float x[4];
            #pragma unroll
            for (int q = 0; q < 4; q++) x[q] = xbuf[nd*STG + lane*4 + q];
            float s = x[0]+x[1]+x[2]+x[3];
            #pragma unroll
            for (int off = 16; off > 0; off >>= 1) s += __shfl_xor_sync(0xffffffffu, s, off);
            float mu = s * (1.f/128.f);
            float ss = 0.f;
            #pragma unroll
            for (int q = 0; q < 4; q++) { float d = x[q]-mu; ss += d*d; }
            #pragma unroll
            for (int off = 16; off > 0; off >>= 1) ss += __shfl_xor_sync(0xffffffffu, ss, off);
            float inv = 1.f / (sqrtf(ss*(1.f/127.f) + EPSF) + EPSF);
            float4 o;
            o.x = gln[lane*4+0]*(x[0]-mu)*inv + hln[lane*4+0];
            o.y = gln[lane*4+1]*(x[1]-mu)*inv + hln[lane*4+1];
            o.z = gln[lane*4+2]*(x[2]-mu)*inv + hln[lane*4+2];
            o.w = gln[lane*4+3]*(x[3]-mu)*inv + hln[lane*4+3];
            *reinterpret_cast<float4*>(&hv[gnode*H_ + lane*4]) = o;
        }
    }
}

// ---------------- residual FFN LN + mask ----------------
__global__ void resln_kernel(float* __restrict__ dst, const float* __restrict__ mask,
                             const float* __restrict__ g1, const float* __restrict__ h1) {
    __shared__ float red[H_];
    int n = blockIdx.x, o = threadIdx.x;
    float x = g_hV[n*H_+o] + g_dh[n*H_+o];
    float mu = block_sum128(x, red) * (1.f/H_);
    float dv = x - mu;
    float var = block_sum128(dv*dv, red) * (1.f/(H_-1));
    float y = g1[o]*dv/(sqrtf(var+EPSF)+EPSF) + h1[o];
    dst[n*H_+o] = mask[n]*y;
}

// ---------------- host ----------------
extern "C" void kernel_launch(void* const* d_in, const int* in_sizes, int n_in,
                              void* d_out, int out_size) {
    const float* X    = (const float*)d_in[0];
    const float* mask = (const float*)d_in[1];
    const float* Wn   = (const float*)d_in[2];
    const float* bn   = (const float*)d_in[3];
    const float* gn   = (const float*)d_in[4];
    const float* hn   = (const float*)d_in[5];
    const float* We   = (const float*)d_in[6];
    const float* be   = (const float*)d_in[7];
    const float* ge   = (const float*)d_in[8];
    const float* he   = (const float*)d_in[9];
    const float* Wv   = (const float*)d_in[10];
    const float* bv   = (const float*)d_in[11];
    const float* Wq   = (const float*)d_in[12];
    const float* bq   = (const float*)d_in[13];
    const float* lW1  = (const float*)d_in[14];
    const float* lb1  = (const float*)d_in[15];
    const float* lW2  = (const float*)d_in[16];
    const float* lb2  = (const float*)d_in[17];
    const float* lW3  = (const float*)d_in[18];
    const float* lb3  = (const float*)d_in[19];
    const float* lWi  = (const float*)d_in[20];
    const float* lbi  = (const float*)d_in[21];
    const float* lWo  = (const float*)d_in[22];
    const float* lbo  = (const float*)d_in[23];
    const float* lg0  = (const float*)d_in[24];
    const float* lh0  = (const float*)d_in[25];
    const float* lg1  = (const float*)d_in[26];
    const float* lh1  = (const float*)d_in[27];

    static int s_init = 0;
    if (!s_init) {
        cudaFuncSetAttribute(mma_gemm, cudaFuncAttributeMaxDynamicSharedMemorySize, SMEM_DYN);
        s_init = 1;
    }

    float *Ebuf, *hV, *nAC, *dh, *b1pad;
    __nv_bfloat16 *wh, *wl, *t0h, *t0l, *t1h, *t1l, *hEh, *hEl, *ffh, *ffl;
    cudaGetSymbolAddress((void**)&Ebuf, g_Ebuf);
    cudaGetSymbolAddress((void**)&hV,   g_hV);
    cudaGetSymbolAddress((void**)&nAC,  g_nAC);
    cudaGetSymbolAddress((void**)&dh,   g_dh);
    cudaGetSymbolAddress((void**)&b1pad,g_b1pad);
    cudaGetSymbolAddress((void**)&wh,   g_wh);
    cudaGetSymbolAddress((void**)&wl,   g_wl);
    cudaGetSymbolAddress((void**)&t0h,  g_t0h);
    cudaGetSymbolAddress((void**)&t0l,  g_t0l);
    cudaGetSymbolAddress((void**)&t1h,  g_t1h);
    cudaGetSymbolAddress((void**)&t1l,  g_t1l);
    cudaGetSymbolAddress((void**)&hEh,  g_hEh);
    cudaGetSymbolAddress((void**)&hEl,  g_hEl);
    cudaGetSymbolAddress((void**)&ffh,  g_ffh);
    cudaGetSymbolAddress((void**)&ffl,  g_ffl);

    auto gemm = [&](const float* Af, const __nv_bfloat16* Ah, const __nv_bfloat16* Al,
                    size_t woff, const float* bias, float* Cf, __nv_bfloat16* Ch, __nv_bfloat16* Cl,
                    int M, int N, int Kd, int ldcv, int mode, int relu,
                    const float* gl, const float* hl, const float* mk, float* hvp) {
        dim3 grid(N/128, M/128);
        mma_gemm<<<grid, 256, SMEM_DYN>>>(Af, Ah, Al, wh+woff, wl+woff, bias,
                                          Cf, Ch, Cl, Kd, ldcv, mode, relu, gl, hl, mk, hvp);
    };

    // weights (single launch)
    prep_all<<<(WTOT+768+255)/256, 256>>>(We, Wq, lW1, lW2, lW3, lWi, lWo, lb1);

    // Phase A
    knn_kernel<<<NNODE, 256>>>(X, mask);
    frames_kernel<<<(NNODE+255)/256, 256>>>(X);
    node_init_kernel<<<NNODE, 128>>>(Wn, bn, gn, hn, Wv, bv);
    edge_feat_kernel<<<(NE+255)/256, 256>>>(X);
    // E = LN(Ebuf @ We + be)  -> t0 (split)
    gemm(Ebuf, nullptr, nullptr, OFF_WE, be, nullptr, t0h, t0l,
         NE, 128, 64, 128, EPI_LN, 0, ge, he, nullptr, nullptr);
    // hE = t0 @ Wq + bq  -> hE (split)
    gemm(nullptr, t0h, t0l, OFF_WQ, bq, nullptr, hEh, hEl,
         NE, 128, 128, 128, EPI_SPLIT, 0, nullptr, nullptr, nullptr, nullptr);

    // Phase B
    for (int l = 0; l < L_; l++) {
        size_t base = OFF_L0 + (size_t)l*LSTRIDE;
        // nAC = hV @ [W1A | W1C] (+b1 on first half)
        gemm(hV, nullptr, nullptr, base + OW1A, b1pad + l*256, nAC, nullptr, nullptr,
             NNODE, 256, 128, 256, EPI_F32, 0, nullptr, nullptr, nullptr, nullptr);
        // t0 = relu(hE @ W1E + nA[center] + nC[neighbor])  (split)
        gemm(nullptr, hEh, hEl, base + OW1E, nullptr, nullptr, t0h, t0l,
             NE, 128, 128, 128, EPI_COMBINE, 0, nullptr, nullptr, nullptr, nullptr);
        // t1 = relu(t0 @ W2 + b2)  (split)
        gemm(nullptr, t0h, t0l, base + OW2, lb2 + l*H_, nullptr, t1h, t1l,
             NE, 128, 128, 128, EPI_SPLIT, 1, nullptr, nullptr, nullptr, nullptr);
        // hV = LN(hV + sum_k((t1 @ W3 + b3) * m_att) / 30)   (fused aggregate)
        gemm(nullptr, t1h, t1l, base + OW3, lb3 + l*H_, nullptr, nullptr, nullptr,
             NE, 128, 128, 128, EPI_AGG, 0, lg0 + l*H_, lh0 + l*H_, mask, hV);
        // ff = relu(hV @ Wi + bi)  (split)
        gemm(hV, nullptr, nullptr, base + OWI, lbi + l*DFF_, nullptr, ffh, ffl,
             NNODE, 512, 128, 512, EPI_SPLIT, 1, nullptr, nullptr, nullptr, nullptr);
        // dh = ff @ Wo + bo
        gemm(nullptr, ffh, ffl, base + OWO, lbo + l*H_, dh, nullptr, nullptr,
             NNODE, 128, 512, 128, EPI_F32, 0, nullptr, nullptr, nullptr, nullptr);
        float* dst = (l == L_-1) ? (float*)d_out : hV;
        resln_kernel<<<NNODE, H_>>>(dst, mask, lg1 + l*H_, lh1 + l*H_);
    }
}